// round 6
// baseline (speedup 1.0000x reference)
#include <cuda_runtime.h>
#include <cuda_bf16.h>
#include <mma.h>
#include <cstdint>

using namespace nvcuda;

// Problem constants
#define N_NODES  100000
#define E_EDGES  1600000
#define M_EDGES  (E_EDGES + N_NODES)   // 1,700,000 with self loops
#define IN_DIM   128
#define D_DIM    128
#define H_HEADS  4
#define C_CH     32
#define N_PAD    100096                // 782 * 128, so direct wmma stores never go OOB

// ---------------- device scratch ----------------
__device__ float g_hin[N_PAD * D_DIM];
__device__ float g_xp [N_PAD * D_DIM];
__device__ float g_asrc[N_NODES * H_HEADS];
__device__ float g_adst[N_NODES * H_HEADS];
__device__ float g_was[IN_DIM * H_HEADS];   // gat_w @ att_src  -> [k][h]
__device__ float g_wad[IN_DIM * H_HEADS];   // gat_w @ att_dst  -> [k][h]
__device__ int   g_cnt[N_NODES];
__device__ int   g_rowstart[N_NODES];
__device__ int   g_cursor[N_NODES];
__device__ int   g_csr[M_EDGES];
__device__ int   g_blksum[256];
__device__ int   g_blkoff[256];
__device__ float g_colsum[D_DIM];
__device__ float g_colsumsq[D_DIM];

__device__ __forceinline__ float lrelu02(float v) { return v > 0.f ? v : 0.2f * v; }

// ---------------- K0: init ----------------
__global__ void init_kernel() {
    int i = blockIdx.x * blockDim.x + threadIdx.x;
    if (i < N_NODES) g_cnt[i] = 0;
    if (i < D_DIM) { g_colsum[i] = 0.f; g_colsumsq[i] = 0.f; }
}

// ---------------- K0b: fold attention vectors into gat_w ----------------
// w_as[k][h] = sum_c gat_w[k][h*32+c] * att_src[h*32+c]   (one block, 512 threads)
__global__ void attw_kernel(const float* __restrict__ gat_w,
                            const float* __restrict__ att_src,
                            const float* __restrict__ att_dst) {
    int t = threadIdx.x;          // t = k*4 + h
    int k = t >> 2, h = t & 3;
    float s = 0.f, d = 0.f;
#pragma unroll
    for (int c = 0; c < 32; c += 4) {
        float4 w = *reinterpret_cast<const float4*>(&gat_w[k * 128 + h * 32 + c]);
        float4 a = *reinterpret_cast<const float4*>(&att_src[h * 32 + c]);
        float4 b = *reinterpret_cast<const float4*>(&att_dst[h * 32 + c]);
        s += w.x * a.x + w.y * a.y + w.z * a.z + w.w * a.w;
        d += w.x * b.x + w.y * b.y + w.z * b.z + w.w * b.w;
    }
    g_was[t] = s;
    g_wad[t] = d;
}

// ---------------- K0c: attention logits directly from x (fp32, warp per node) ----------------
__global__ void attlogit_kernel(const float* __restrict__ x) {
    int n = (blockIdx.x * blockDim.x + threadIdx.x) >> 5;
    int lane = threadIdx.x & 31;
    if (n >= N_NODES) return;
    float4 xv = reinterpret_cast<const float4*>(x)[n * 32 + lane];
    float4 as = make_float4(0.f, 0.f, 0.f, 0.f);
    float4 ad = make_float4(0.f, 0.f, 0.f, 0.f);
#pragma unroll
    for (int q = 0; q < 4; q++) {
        int k = lane * 4 + q;
        float xk = (q == 0) ? xv.x : (q == 1) ? xv.y : (q == 2) ? xv.z : xv.w;
        float4 ws = *reinterpret_cast<const float4*>(&g_was[k * 4]);
        float4 wd = *reinterpret_cast<const float4*>(&g_wad[k * 4]);
        as.x += xk * ws.x; as.y += xk * ws.y; as.z += xk * ws.z; as.w += xk * ws.w;
        ad.x += xk * wd.x; ad.y += xk * wd.y; ad.z += xk * wd.z; ad.w += xk * wd.w;
    }
#pragma unroll
    for (int o = 16; o > 0; o >>= 1) {
        as.x += __shfl_xor_sync(0xffffffffu, as.x, o);
        as.y += __shfl_xor_sync(0xffffffffu, as.y, o);
        as.z += __shfl_xor_sync(0xffffffffu, as.z, o);
        as.w += __shfl_xor_sync(0xffffffffu, as.w, o);
        ad.x += __shfl_xor_sync(0xffffffffu, ad.x, o);
        ad.y += __shfl_xor_sync(0xffffffffu, ad.y, o);
        ad.z += __shfl_xor_sync(0xffffffffu, ad.z, o);
        ad.w += __shfl_xor_sync(0xffffffffu, ad.w, o);
    }
    if (lane == 0) {
        reinterpret_cast<float4*>(g_asrc)[n] = as;
        reinterpret_cast<float4*>(g_adst)[n] = ad;
    }
}

// ---------------- K1: wmma tf32 GEMM, direct global store ----------------
// grid = (ceil(N/128), 2): y=0 -> g_hin = x@lin_w ; y=1 -> g_xp = x@gat_w.
// 256 threads (8 warps). BM=128, BN=128, full K in smem for x; W double-buffered in 32-K chunks.
#define LDA2 132   // x smem stride (128 + 4)
#define LDB2 136   // W chunk stride (128 + 8)
#define XS_FLOATS (128 * LDA2)
#define WS_FLOATS (32 * LDB2)
#define GEMM_SMEM ((XS_FLOATS + 2 * WS_FLOATS) * 4)   // 67584 + 34816 = 102400 B

__global__ __launch_bounds__(256) void gemm_kernel(
    const float* __restrict__ x, const float* __restrict__ lin_w,
    const float* __restrict__ gat_w)
{
    extern __shared__ float sm[];
    float* xs = sm;                          // [128][LDA2]
    float* ws0 = sm + XS_FLOATS;             // [32][LDB2] x2
    const bool is_gat = (blockIdx.y != 0);
    const float* W = is_gat ? gat_w : lin_w;
    float* OUT = is_gat ? g_xp : g_hin;
    const int n0 = blockIdx.x * 128;
    const int tid = threadIdx.x, wid = tid >> 5;
    const int wr = wid & 3;                  // rows wr*32..+31
    const int wc = wid >> 2;                 // cols wc*64..+63

    // load full x tile [128][128]
#pragma unroll
    for (int i = 0; i < 16; i++) {
        int f = tid + i * 256;               // float4 over 128*32
        int row = f >> 5, c4 = f & 31;
        float4 v = make_float4(0.f, 0.f, 0.f, 0.f);
        if (n0 + row < N_NODES)
            v = reinterpret_cast<const float4*>(x)[(n0 + row) * 32 + c4];
        *reinterpret_cast<float4*>(&xs[row * LDA2 + c4 * 4]) = v;
    }
    // load W chunk 0
#pragma unroll
    for (int i = 0; i < 4; i++) {
        int f = tid + i * 256;               // float4 over 32*32
        int row = f >> 5, c4 = f & 31;
        *reinterpret_cast<float4*>(&ws0[row * LDB2 + c4 * 4]) =
            reinterpret_cast<const float4*>(W)[row * 32 + c4];
    }
    __syncthreads();

    wmma::fragment<wmma::accumulator, 16, 16, 8, float> acc[2][4];
#pragma unroll
    for (int i = 0; i < 2; i++)
#pragma unroll
        for (int j = 0; j < 4; j++) wmma::fill_fragment(acc[i][j], 0.0f);

    for (int kc = 0; kc < 4; kc++) {
        float* cur = ws0 + (kc & 1) * WS_FLOATS;
        float* nxt = ws0 + ((kc + 1) & 1) * WS_FLOATS;
        if (kc < 3) {
#pragma unroll
            for (int i = 0; i < 4; i++) {
                int f = tid + i * 256;
                int row = f >> 5, c4 = f & 31;
                *reinterpret_cast<float4*>(&nxt[row * LDB2 + c4 * 4]) =
                    reinterpret_cast<const float4*>(W)[((kc + 1) * 32 + row) * 32 + c4];
            }
        }
#pragma unroll
        for (int kk = 0; kk < 4; kk++) {
            wmma::fragment<wmma::matrix_a, 16, 16, 8, wmma::precision::tf32, wmma::row_major> a[2];
            wmma::fragment<wmma::matrix_b, 16, 16, 8, wmma::precision::tf32, wmma::row_major> b[4];
#pragma unroll
            for (int i = 0; i < 2; i++) {
                wmma::load_matrix_sync(a[i], &xs[(wr * 32 + i * 16) * LDA2 + kc * 32 + kk * 8], LDA2);
#pragma unroll
                for (int t = 0; t < a[i].num_elements; t++)
                    a[i].x[t] = wmma::__float_to_tf32(a[i].x[t]);
            }
#pragma unroll
            for (int j = 0; j < 4; j++) {
                wmma::load_matrix_sync(b[j], &cur[(kk * 8) * LDB2 + wc * 64 + j * 16], LDB2);
#pragma unroll
                for (int t = 0; t < b[j].num_elements; t++)
                    b[j].x[t] = wmma::__float_to_tf32(b[j].x[t]);
            }
#pragma unroll
            for (int i = 0; i < 2; i++)
#pragma unroll
                for (int j = 0; j < 4; j++)
                    wmma::mma_sync(acc[i][j], a[i], b[j], acc[i][j]);
        }
        __syncthreads();
    }

    // direct global store (arrays padded to N_PAD rows -> no OOB)
#pragma unroll
    for (int i = 0; i < 2; i++)
#pragma unroll
        for (int j = 0; j < 4; j++)
            wmma::store_matrix_sync(&OUT[(uint64_t)(n0 + wr * 32 + i * 16) * 128 + wc * 64 + j * 16],
                                    acc[i][j], 128, wmma::mem_row_major);
}

// ---------------- K3: degree histogram ----------------
__global__ void count_kernel(const int* __restrict__ ei) {
    int i = blockIdx.x * blockDim.x + threadIdx.x;
    if (i >= M_EDGES) return;
    int d = (i < E_EDGES) ? ei[E_EDGES + i] : (i - E_EDGES);
    atomicAdd(&g_cnt[d], 1);
}

// ---------------- K4-K6: exclusive scan ----------------
__global__ void scanA_kernel() {
    __shared__ int sh[256];
    int t = threadIdx.x;
    int base = blockIdx.x * 1024 + t * 4;
    int v0 = 0, v1 = 0, v2 = 0, v3 = 0;
    if (base + 0 < N_NODES) v0 = g_cnt[base + 0];
    if (base + 1 < N_NODES) v1 = g_cnt[base + 1];
    if (base + 2 < N_NODES) v2 = g_cnt[base + 2];
    if (base + 3 < N_NODES) v3 = g_cnt[base + 3];
    int s = v0 + v1 + v2 + v3;
    sh[t] = s; __syncthreads();
    for (int off = 1; off < 256; off <<= 1) {
        int u = (t >= off) ? sh[t - off] : 0; __syncthreads();
        sh[t] += u; __syncthreads();
    }
    int run = sh[t] - s;
    if (base + 0 < N_NODES) g_rowstart[base + 0] = run; run += v0;
    if (base + 1 < N_NODES) g_rowstart[base + 1] = run; run += v1;
    if (base + 2 < N_NODES) g_rowstart[base + 2] = run; run += v2;
    if (base + 3 < N_NODES) g_rowstart[base + 3] = run;
    if (t == 255) g_blksum[blockIdx.x] = sh[255];
}

__global__ void scanB_kernel(int nb) {
    __shared__ int sh[256];
    int t = threadIdx.x;
    int v = (t < nb) ? g_blksum[t] : 0;
    sh[t] = v; __syncthreads();
    for (int off = 1; off < 256; off <<= 1) {
        int u = (t >= off) ? sh[t - off] : 0; __syncthreads();
        sh[t] += u; __syncthreads();
    }
    if (t < nb) g_blkoff[t] = sh[t] - v;
}

__global__ void scanC_kernel() {
    int t = threadIdx.x;
    int off = g_blkoff[blockIdx.x];
#pragma unroll
    for (int j = 0; j < 4; j++) {
        int i = blockIdx.x * 1024 + t * 4 + j;
        if (i < N_NODES) {
            int r = g_rowstart[i] + off;
            g_rowstart[i] = r;
            g_cursor[i] = r;
        }
    }
}

// ---------------- K7: scatter edges into CSR ----------------
__global__ void scatter_kernel(const int* __restrict__ ei) {
    int i = blockIdx.x * blockDim.x + threadIdx.x;
    if (i >= M_EDGES) return;
    int s, d;
    if (i < E_EDGES) { s = ei[i]; d = ei[E_EDGES + i]; }
    else             { s = d = i - E_EDGES; }
    int pos = atomicAdd(&g_cursor[d], 1);
    g_csr[pos] = s;
}

// ---------------- K8: single-pass softmax + aggregation (one warp per dst node) ----------------
// acc = sum_e w_e * xp[src_e], den = sum_e w_e, out = acc/den + bias. Identical math to
// two-pass since alpha_e = w_e/den. Lanes in an 8-lane head group redundantly compute den.
__global__ void agg_kernel(const float* __restrict__ gat_bias, float* __restrict__ out) {
    int n = (blockIdx.x * blockDim.x + threadIdx.x) >> 5;
    int lane = threadIdx.x & 31;
    if (n >= N_NODES) return;
    int rs = g_rowstart[n];
    int deg = g_cnt[n];
    int h = lane >> 3;
    float ad_h = g_adst[n * 4 + h];

    float den = 0.f;
    float4 acc = make_float4(0.f, 0.f, 0.f, 0.f);
    int e = rs, end = rs + deg;
    for (; e + 4 <= end; e += 4) {
        int s0 = g_csr[e], s1 = g_csr[e + 1], s2 = g_csr[e + 2], s3 = g_csr[e + 3];
        float a0 = g_asrc[s0 * 4 + h], a1 = g_asrc[s1 * 4 + h];
        float a2 = g_asrc[s2 * 4 + h], a3 = g_asrc[s3 * 4 + h];
        float4 x0 = reinterpret_cast<const float4*>(g_xp)[s0 * 32 + lane];
        float4 x1 = reinterpret_cast<const float4*>(g_xp)[s1 * 32 + lane];
        float4 x2 = reinterpret_cast<const float4*>(g_xp)[s2 * 32 + lane];
        float4 x3 = reinterpret_cast<const float4*>(g_xp)[s3 * 32 + lane];
        float w0 = __expf(lrelu02(a0 + ad_h));
        float w1 = __expf(lrelu02(a1 + ad_h));
        float w2 = __expf(lrelu02(a2 + ad_h));
        float w3 = __expf(lrelu02(a3 + ad_h));
        den += (w0 + w1) + (w2 + w3);
        acc.x += w0 * x0.x + w1 * x1.x + w2 * x2.x + w3 * x3.x;
        acc.y += w0 * x0.y + w1 * x1.y + w2 * x2.y + w3 * x3.y;
        acc.z += w0 * x0.z + w1 * x1.z + w2 * x2.z + w3 * x3.z;
        acc.w += w0 * x0.w + w1 * x1.w + w2 * x2.w + w3 * x3.w;
    }
    for (; e < end; e++) {
        int s = g_csr[e];
        float w = __expf(lrelu02(g_asrc[s * 4 + h] + ad_h));
        float4 xv = reinterpret_cast<const float4*>(g_xp)[s * 32 + lane];
        den += w;
        acc.x += w * xv.x; acc.y += w * xv.y;
        acc.z += w * xv.z; acc.w += w * xv.w;
    }
    float inv = 1.0f / den;                    // den > 0 guaranteed by self loop
    float4 b = reinterpret_cast<const float4*>(gat_bias)[lane];
    acc.x = acc.x * inv + b.x; acc.y = acc.y * inv + b.y;
    acc.z = acc.z * inv + b.z; acc.w = acc.w * inv + b.w;
    reinterpret_cast<float4*>(out)[n * 32 + lane] = acc;
}

// ---------------- K9: column statistics for BatchNorm ----------------
__global__ void colstats_kernel(const float* __restrict__ y) {
    int t = threadIdx.x;
    float s = 0.f, ss = 0.f;
    for (int r = blockIdx.x; r < N_NODES; r += gridDim.x) {
        float v = y[r * 128 + t];
        s += v; ss += v * v;
    }
    atomicAdd(&g_colsum[t], s);
    atomicAdd(&g_colsumsq[t], ss);
}

// ---------------- K10: BN + ELU + residual (+ lin bias, moved out of GEMM) ----------------
__global__ void final_kernel(float* __restrict__ out,
                             const float* __restrict__ gamma, const float* __restrict__ beta,
                             const float* __restrict__ lin_b) {
    int i = blockIdx.x * blockDim.x + threadIdx.x;
    if (i >= N_NODES * 128) return;
    int c = i & 127;
    const float invN = 1.0f / (float)N_NODES;
    float mu = g_colsum[c] * invN;
    float var = g_colsumsq[c] * invN - mu * mu;
    float y = out[i];
    float t = (y - mu) * rsqrtf(var + 1e-5f) * gamma[c] + beta[c];
    float h = t > 0.f ? t : expm1f(t);
    out[i] = g_hin[i] + lin_b[c] + h;
}

// ---------------- launch ----------------
extern "C" void kernel_launch(void* const* d_in, const int* in_sizes, int n_in,
                              void* d_out, int out_size) {
    const float* x        = (const float*)d_in[0];
    const int*   ei       = (const int*)  d_in[1];
    const float* lin_w    = (const float*)d_in[2];
    const float* lin_b    = (const float*)d_in[3];
    const float* gat_w    = (const float*)d_in[4];
    const float* att_src  = (const float*)d_in[5];
    const float* att_dst  = (const float*)d_in[6];
    const float* gat_bias = (const float*)d_in[7];
    const float* bn_gamma = (const float*)d_in[8];
    const float* bn_beta  = (const float*)d_in[9];
    float* out = (float*)d_out;

    cudaFuncSetAttribute(gemm_kernel, cudaFuncAttributeMaxDynamicSharedMemorySize, GEMM_SMEM);

    const int NB = (N_NODES + 1023) / 1024;

    init_kernel<<<(N_NODES + 255) / 256, 256>>>();
    attw_kernel<<<1, 512>>>(gat_w, att_src, att_dst);
    gemm_kernel<<<dim3((N_NODES + 127) / 128, 2), 256, GEMM_SMEM>>>(x, lin_w, gat_w);
    attlogit_kernel<<<(N_NODES + 7) / 8, 256>>>(x);
    count_kernel<<<(M_EDGES + 255) / 256, 256>>>(ei);
    scanA_kernel<<<NB, 256>>>();
    scanB_kernel<<<1, 256>>>(NB);
    scanC_kernel<<<NB, 256>>>();
    scatter_kernel<<<(M_EDGES + 255) / 256, 256>>>(ei);
    agg_kernel<<<(N_NODES + 7) / 8, 256>>>(gat_bias, out);
    colstats_kernel<<<512, 128>>>(out);
    final_kernel<<<(N_NODES * 128 + 255) / 256, 256>>>(out, bn_gamma, bn_beta, lin_b);
}

// round 9
// speedup vs baseline: 1.2839x; 1.2839x over previous
#include <cuda_runtime.h>
#include <cuda_bf16.h>
#include <cuda_fp16.h>
#include <mma.h>
#include <cstdint>

using namespace nvcuda;

// Problem constants
#define N_NODES  100000
#define E_EDGES  1600000
#define M_EDGES  (E_EDGES + N_NODES)   // 1,700,000 with self loops
#define IN_DIM   128
#define D_DIM    128
#define H_HEADS  4
#define C_CH     32

// ---------------- device scratch ----------------
__device__ float  g_hin[N_NODES * D_DIM];
__device__ __half g_xp [N_NODES * D_DIM];   // fp16 payload: only consumed by edge gather
__device__ float  g_asrc[N_NODES * H_HEADS];
__device__ float  g_adst[N_NODES * H_HEADS];
__device__ int    g_cnt[N_NODES];
__device__ int    g_rowstart[N_NODES];
__device__ int    g_cursor[N_NODES];
__device__ int    g_csr[M_EDGES];
__device__ int    g_blksum[256];
__device__ int    g_blkoff[256];
__device__ float  g_colsum[D_DIM];
__device__ float  g_colsumsq[D_DIM];

__device__ __forceinline__ float lrelu02(float v) { return v > 0.f ? v : 0.2f * v; }

// ---------------- K0: init ----------------
__global__ void init_kernel() {
    int i = blockIdx.x * blockDim.x + threadIdx.x;
    if (i < N_NODES) g_cnt[i] = 0;
    if (i < D_DIM) { g_colsum[i] = 0.f; g_colsumsq[i] = 0.f; }
}

// ---------------- K1: wmma tf32 GEMM (+ fused attention logits on gat half) ----------------
// grid = (ceil(N/128), 2): y=0 -> h_in = x@lin_w + lin_b ; y=1 -> xp(fp16) = x@gat_w, + att logits.
// Block 256 thr (8 warps). BM=128, BN=128, BK=32. Warp tile 32x64 (2x4 frags of 16x16x8).
#define LDA 40    // 32 + 8 pad (floats)
#define LDB 136   // 128 + 8 pad
#define LDC_S 132 // 128 + 4 pad
#define GEMM_SMEM (128 * LDC_S * 4)   // 67584 B; load buffers (128*40 + 32*136 = 37.9KB) overlap

__global__ __launch_bounds__(256) void gemm_kernel(
    const float* __restrict__ x, const float* __restrict__ lin_w,
    const float* __restrict__ lin_b, const float* __restrict__ gat_w,
    const float* __restrict__ att_src, const float* __restrict__ att_dst)
{
    extern __shared__ float sm[];
    float* xs = sm;                  // [128][LDA]
    float* ws = sm + 128 * LDA;      // [32][LDB]
    float* cs = sm;                  // epilogue reuse [128][LDC_S]

    const bool is_gat = (blockIdx.y != 0);
    const float* W = is_gat ? gat_w : lin_w;
    const int n0 = blockIdx.x * 128;
    const int tid = threadIdx.x, wid = tid >> 5, lane = tid & 31;
    const int wr = wid & 3;          // warp row group: rows wr*32..wr*32+31
    const int wc = wid >> 2;         // warp col group: cols wc*64..wc*64+63

    wmma::fragment<wmma::accumulator, 16, 16, 8, float> acc[2][4];
#pragma unroll
    for (int i = 0; i < 2; i++)
#pragma unroll
        for (int j = 0; j < 4; j++) wmma::fill_fragment(acc[i][j], 0.0f);

    for (int kc = 0; kc < 4; kc++) {
        __syncthreads();
        // load x chunk [128 rows][32 cols] as float4
#pragma unroll
        for (int i = 0; i < 4; i++) {
            int f = tid + i * 256;              // float4 index over 128*8
            int row = f >> 3, c4 = f & 7;
            float4 v = make_float4(0.f, 0.f, 0.f, 0.f);
            if (n0 + row < N_NODES)
                v = reinterpret_cast<const float4*>(x)[(n0 + row) * 32 + kc * 8 + c4];
            *reinterpret_cast<float4*>(&xs[row * LDA + c4 * 4]) = v;
        }
        // load W chunk [32 k][128 j] as float4
#pragma unroll
        for (int i = 0; i < 4; i++) {
            int f = tid + i * 256;              // float4 index over 32*32
            int row = f >> 5, c4 = f & 31;
            *reinterpret_cast<float4*>(&ws[row * LDB + c4 * 4]) =
                reinterpret_cast<const float4*>(W)[(kc * 32 + row) * 32 + c4];
        }
        __syncthreads();

#pragma unroll
        for (int kk = 0; kk < 4; kk++) {
            wmma::fragment<wmma::matrix_a, 16, 16, 8, wmma::precision::tf32, wmma::row_major> a[2];
            wmma::fragment<wmma::matrix_b, 16, 16, 8, wmma::precision::tf32, wmma::row_major> b[4];
#pragma unroll
            for (int i = 0; i < 2; i++) {
                wmma::load_matrix_sync(a[i], &xs[(wr * 32 + i * 16) * LDA + kk * 8], LDA);
#pragma unroll
                for (int t = 0; t < a[i].num_elements; t++)
                    a[i].x[t] = wmma::__float_to_tf32(a[i].x[t]);
            }
#pragma unroll
            for (int j = 0; j < 4; j++) {
                wmma::load_matrix_sync(b[j], &ws[(kk * 8) * LDB + wc * 64 + j * 16], LDB);
#pragma unroll
                for (int t = 0; t < b[j].num_elements; t++)
                    b[j].x[t] = wmma::__float_to_tf32(b[j].x[t]);
            }
#pragma unroll
            for (int i = 0; i < 2; i++)
#pragma unroll
                for (int j = 0; j < 4; j++)
                    wmma::mma_sync(acc[i][j], a[i], b[j], acc[i][j]);
        }
    }

    __syncthreads();
#pragma unroll
    for (int i = 0; i < 2; i++)
#pragma unroll
        for (int j = 0; j < 4; j++)
            wmma::store_matrix_sync(&cs[(wr * 32 + i * 16) * LDC_S + wc * 64 + j * 16],
                                    acc[i][j], LDC_S, wmma::mem_row_major);
    __syncthreads();

    // epilogue: warp handles 16 rows; lane covers 4 cols (lane*4 .. lane*4+3)
    float4 b4 = make_float4(0.f, 0.f, 0.f, 0.f);
    float4 as4 = b4, ad4 = b4;
    if (is_gat) {
        as4 = *reinterpret_cast<const float4*>(&att_src[lane * 4]);
        ad4 = *reinterpret_cast<const float4*>(&att_dst[lane * 4]);
    } else {
        b4 = *reinterpret_cast<const float4*>(&lin_b[lane * 4]);
    }
    const int h = lane >> 3;     // head of this lane's columns
#pragma unroll
    for (int r = 0; r < 16; r++) {
        int row = wid * 16 + r;
        int n = n0 + row;
        float4 v = *reinterpret_cast<const float4*>(&cs[row * LDC_S + lane * 4]);
        if (!is_gat) {
            if (n < N_NODES) {
                v.x += b4.x; v.y += b4.y; v.z += b4.z; v.w += b4.w;
                *reinterpret_cast<float4*>(&g_hin[n * 128 + lane * 4]) = v;
            }
        } else {
            // logits from fp32 values (before fp16 conversion)
            float s = v.x * as4.x + v.y * as4.y + v.z * as4.z + v.w * as4.w;
            float d = v.x * ad4.x + v.y * ad4.y + v.z * ad4.z + v.w * ad4.w;
#pragma unroll
            for (int o = 4; o > 0; o >>= 1) {      // reduce within 8-lane head group
                s += __shfl_xor_sync(0xffffffffu, s, o);
                d += __shfl_xor_sync(0xffffffffu, d, o);
            }
            if (n < N_NODES) {
                __half2 h0 = __floats2half2_rn(v.x, v.y);
                __half2 h1 = __floats2half2_rn(v.z, v.w);
                uint2 p;
                p.x = *reinterpret_cast<uint32_t*>(&h0);
                p.y = *reinterpret_cast<uint32_t*>(&h1);
                reinterpret_cast<uint2*>(g_xp)[n * 32 + lane] = p;  // 8B per lane
                if ((lane & 7) == 0) {
                    g_asrc[n * 4 + h] = s;
                    g_adst[n * 4 + h] = d;
                }
            }
        }
    }
}

// ---------------- K3: degree histogram ----------------
__global__ void count_kernel(const int* __restrict__ ei) {
    int i = blockIdx.x * blockDim.x + threadIdx.x;
    if (i >= M_EDGES) return;
    int d = (i < E_EDGES) ? ei[E_EDGES + i] : (i - E_EDGES);
    atomicAdd(&g_cnt[d], 1);
}

// ---------------- K4-K6: exclusive scan ----------------
__global__ void scanA_kernel() {
    __shared__ int sh[256];
    int t = threadIdx.x;
    int base = blockIdx.x * 1024 + t * 4;
    int v0 = 0, v1 = 0, v2 = 0, v3 = 0;
    if (base + 0 < N_NODES) v0 = g_cnt[base + 0];
    if (base + 1 < N_NODES) v1 = g_cnt[base + 1];
    if (base + 2 < N_NODES) v2 = g_cnt[base + 2];
    if (base + 3 < N_NODES) v3 = g_cnt[base + 3];
    int s = v0 + v1 + v2 + v3;
    sh[t] = s; __syncthreads();
    for (int off = 1; off < 256; off <<= 1) {
        int u = (t >= off) ? sh[t - off] : 0; __syncthreads();
        sh[t] += u; __syncthreads();
    }
    int run = sh[t] - s;
    if (base + 0 < N_NODES) g_rowstart[base + 0] = run; run += v0;
    if (base + 1 < N_NODES) g_rowstart[base + 1] = run; run += v1;
    if (base + 2 < N_NODES) g_rowstart[base + 2] = run; run += v2;
    if (base + 3 < N_NODES) g_rowstart[base + 3] = run;
    if (t == 255) g_blksum[blockIdx.x] = sh[255];
}

__global__ void scanB_kernel(int nb) {
    __shared__ int sh[256];
    int t = threadIdx.x;
    int v = (t < nb) ? g_blksum[t] : 0;
    sh[t] = v; __syncthreads();
    for (int off = 1; off < 256; off <<= 1) {
        int u = (t >= off) ? sh[t - off] : 0; __syncthreads();
        sh[t] += u; __syncthreads();
    }
    if (t < nb) g_blkoff[t] = sh[t] - v;
}

__global__ void scanC_kernel() {
    int t = threadIdx.x;
    int off = g_blkoff[blockIdx.x];
#pragma unroll
    for (int j = 0; j < 4; j++) {
        int i = blockIdx.x * 1024 + t * 4 + j;
        if (i < N_NODES) {
            int r = g_rowstart[i] + off;
            g_rowstart[i] = r;
            g_cursor[i] = r;
        }
    }
}

// ---------------- K7: scatter edges into CSR ----------------
__global__ void scatter_kernel(const int* __restrict__ ei) {
    int i = blockIdx.x * blockDim.x + threadIdx.x;
    if (i >= M_EDGES) return;
    int s, d;
    if (i < E_EDGES) { s = ei[i]; d = ei[E_EDGES + i]; }
    else             { s = d = i - E_EDGES; }
    int pos = atomicAdd(&g_cursor[d], 1);
    g_csr[pos] = s;
}

// ---------------- K8: single-pass softmax + aggregation (one warp per dst node) ----------------
// acc = sum_e w_e * xp[src_e], den = sum_e w_e, out = acc/den + bias. Identical math to
// two-pass softmax since alpha_e = w_e/den. xp gathered as fp16 (8B/lane), accumulated fp32.
__global__ void agg_kernel(const float* __restrict__ gat_bias, float* __restrict__ out) {
    int n = (blockIdx.x * blockDim.x + threadIdx.x) >> 5;
    int lane = threadIdx.x & 31;
    if (n >= N_NODES) return;
    int rs = g_rowstart[n];
    int deg = g_cnt[n];
    int h = lane >> 3;
    float ad_h = g_adst[n * 4 + h];
    const uint2* xp2 = reinterpret_cast<const uint2*>(g_xp);

    float den = 0.f;
    float4 acc = make_float4(0.f, 0.f, 0.f, 0.f);
    int e = rs, end = rs + deg;
    for (; e + 4 <= end; e += 4) {
        int s0 = g_csr[e], s1 = g_csr[e + 1], s2 = g_csr[e + 2], s3 = g_csr[e + 3];
        float a0 = g_asrc[s0 * 4 + h], a1 = g_asrc[s1 * 4 + h];
        float a2 = g_asrc[s2 * 4 + h], a3 = g_asrc[s3 * 4 + h];
        uint2 p0 = xp2[s0 * 32 + lane];
        uint2 p1 = xp2[s1 * 32 + lane];
        uint2 p2 = xp2[s2 * 32 + lane];
        uint2 p3 = xp2[s3 * 32 + lane];
        float w0 = __expf(lrelu02(a0 + ad_h));
        float w1 = __expf(lrelu02(a1 + ad_h));
        float w2 = __expf(lrelu02(a2 + ad_h));
        float w3 = __expf(lrelu02(a3 + ad_h));
        den += (w0 + w1) + (w2 + w3);
        float2 l0 = __half22float2(*reinterpret_cast<__half2*>(&p0.x));
        float2 m0 = __half22float2(*reinterpret_cast<__half2*>(&p0.y));
        float2 l1 = __half22float2(*reinterpret_cast<__half2*>(&p1.x));
        float2 m1 = __half22float2(*reinterpret_cast<__half2*>(&p1.y));
        float2 l2 = __half22float2(*reinterpret_cast<__half2*>(&p2.x));
        float2 m2 = __half22float2(*reinterpret_cast<__half2*>(&p2.y));
        float2 l3 = __half22float2(*reinterpret_cast<__half2*>(&p3.x));
        float2 m3 = __half22float2(*reinterpret_cast<__half2*>(&p3.y));
        acc.x += w0 * l0.x + w1 * l1.x + w2 * l2.x + w3 * l3.x;
        acc.y += w0 * l0.y + w1 * l1.y + w2 * l2.y + w3 * l3.y;
        acc.z += w0 * m0.x + w1 * m1.x + w2 * m2.x + w3 * m3.x;
        acc.w += w0 * m0.y + w1 * m1.y + w2 * m2.y + w3 * m3.y;
    }
    for (; e < end; e++) {
        int s = g_csr[e];
        float w = __expf(lrelu02(g_asrc[s * 4 + h] + ad_h));
        uint2 p = xp2[s * 32 + lane];
        float2 l = __half22float2(*reinterpret_cast<__half2*>(&p.x));
        float2 m = __half22float2(*reinterpret_cast<__half2*>(&p.y));
        den += w;
        acc.x += w * l.x; acc.y += w * l.y;
        acc.z += w * m.x; acc.w += w * m.y;
    }
    float inv = 1.0f / den;                    // den > 0 guaranteed by self loop
    float4 b = reinterpret_cast<const float4*>(gat_bias)[lane];
    acc.x = acc.x * inv + b.x; acc.y = acc.y * inv + b.y;
    acc.z = acc.z * inv + b.z; acc.w = acc.w * inv + b.w;
    reinterpret_cast<float4*>(out)[n * 32 + lane] = acc;
}

// ---------------- K9: column statistics for BatchNorm ----------------
__global__ void colstats_kernel(const float* __restrict__ y) {
    int t = threadIdx.x;
    float s = 0.f, ss = 0.f;
    for (int r = blockIdx.x; r < N_NODES; r += gridDim.x) {
        float v = y[r * 128 + t];
        s += v; ss += v * v;
    }
    atomicAdd(&g_colsum[t], s);
    atomicAdd(&g_colsumsq[t], ss);
}

// ---------------- K10: BN + ELU + residual ----------------
__global__ void final_kernel(float* __restrict__ out,
                             const float* __restrict__ gamma, const float* __restrict__ beta) {
    int i = blockIdx.x * blockDim.x + threadIdx.x;
    if (i >= N_NODES * 128) return;
    int c = i & 127;
    const float invN = 1.0f / (float)N_NODES;
    float mu = g_colsum[c] * invN;
    float var = g_colsumsq[c] * invN - mu * mu;
    float y = out[i];
    float t = (y - mu) * rsqrtf(var + 1e-5f) * gamma[c] + beta[c];
    float h = t > 0.f ? t : expm1f(t);
    out[i] = g_hin[i] + h;
}

// ---------------- launch ----------------
extern "C" void kernel_launch(void* const* d_in, const int* in_sizes, int n_in,
                              void* d_out, int out_size) {
    const float* x        = (const float*)d_in[0];
    const int*   ei       = (const int*)  d_in[1];
    const float* lin_w    = (const float*)d_in[2];
    const float* lin_b    = (const float*)d_in[3];
    const float* gat_w    = (const float*)d_in[4];
    const float* att_src  = (const float*)d_in[5];
    const float* att_dst  = (const float*)d_in[6];
    const float* gat_bias = (const float*)d_in[7];
    const float* bn_gamma = (const float*)d_in[8];
    const float* bn_beta  = (const float*)d_in[9];
    float* out = (float*)d_out;

    cudaFuncSetAttribute(gemm_kernel, cudaFuncAttributeMaxDynamicSharedMemorySize, GEMM_SMEM);

    const int NB = (N_NODES + 1023) / 1024;

    init_kernel<<<(N_NODES + 255) / 256, 256>>>();
    gemm_kernel<<<dim3((N_NODES + 127) / 128, 2), 256, GEMM_SMEM>>>(
        x, lin_w, lin_b, gat_w, att_src, att_dst);
    count_kernel<<<(M_EDGES + 255) / 256, 256>>>(ei);
    scanA_kernel<<<NB, 256>>>();
    scanB_kernel<<<1, 256>>>(NB);
    scanC_kernel<<<NB, 256>>>();
    scatter_kernel<<<(M_EDGES + 255) / 256, 256>>>(ei);
    agg_kernel<<<(N_NODES + 7) / 8, 256>>>(gat_bias, out);
    colstats_kernel<<<512, 128>>>(out);
    final_kernel<<<(N_NODES * 128 + 255) / 256, 256>>>(out, bn_gamma, bn_beta);
}

// round 10
// speedup vs baseline: 1.3409x; 1.0444x over previous
#include <cuda_runtime.h>
#include <cuda_bf16.h>
#include <cuda_fp16.h>
#include <mma.h>
#include <cstdint>

using namespace nvcuda;

// Problem constants
#define N_NODES  100000
#define E_EDGES  1600000
#define M_EDGES  (E_EDGES + N_NODES)   // 1,700,000 with self loops
#define IN_DIM   128
#define D_DIM    128
#define H_HEADS  4
#define C_CH     32

// ---------------- device scratch ----------------
__device__ float  g_hin[N_NODES * D_DIM];
__device__ __half g_xp [N_NODES * D_DIM];   // fp16 payload: only consumed by edge gather
__device__ float  g_asrc[N_NODES * H_HEADS];
__device__ float  g_adst[N_NODES * H_HEADS];
__device__ int    g_cnt[N_NODES];
__device__ int    g_rowstart[N_NODES];
__device__ int    g_cursor[N_NODES];
__device__ int    g_csr[M_EDGES];
__device__ int    g_blksum[256];
__device__ int    g_blkoff[256];
__device__ float  g_colsum[D_DIM];
__device__ float  g_colsumsq[D_DIM];

__device__ __forceinline__ float lrelu02(float v) { return v > 0.f ? v : 0.2f * v; }

// ---------------- K0: init (runs on edge branch; also zeroes BN accumulators) ----------------
__global__ void init_kernel() {
    int i = blockIdx.x * blockDim.x + threadIdx.x;
    if (i < N_NODES) g_cnt[i] = 0;
    if (i < D_DIM) { g_colsum[i] = 0.f; g_colsumsq[i] = 0.f; }
}

// ---------------- K1: wmma tf32 GEMM (+ fused attention logits on gat half) ----------------
// grid = (ceil(N/128), 2): y=0 -> h_in = x@lin_w + lin_b ; y=1 -> xp(fp16) = x@gat_w, + att logits.
// Block 256 thr (8 warps). BM=128, BN=128, BK=32. Warp tile 32x64 (2x4 frags of 16x16x8).
#define LDA 40    // 32 + 8 pad (floats)
#define LDB 136   // 128 + 8 pad
#define LDC_S 132 // 128 + 4 pad
#define GEMM_SMEM (128 * LDC_S * 4)   // 67584 B; load buffers (128*40 + 32*136 = 37.9KB) overlap

__global__ __launch_bounds__(256) void gemm_kernel(
    const float* __restrict__ x, const float* __restrict__ lin_w,
    const float* __restrict__ lin_b, const float* __restrict__ gat_w,
    const float* __restrict__ att_src, const float* __restrict__ att_dst)
{
    extern __shared__ float sm[];
    float* xs = sm;                  // [128][LDA]
    float* ws = sm + 128 * LDA;      // [32][LDB]
    float* cs = sm;                  // epilogue reuse [128][LDC_S]

    const bool is_gat = (blockIdx.y != 0);
    const float* W = is_gat ? gat_w : lin_w;
    const int n0 = blockIdx.x * 128;
    const int tid = threadIdx.x, wid = tid >> 5, lane = tid & 31;
    const int wr = wid & 3;          // warp row group: rows wr*32..wr*32+31
    const int wc = wid >> 2;         // warp col group: cols wc*64..wc*64+63

    wmma::fragment<wmma::accumulator, 16, 16, 8, float> acc[2][4];
#pragma unroll
    for (int i = 0; i < 2; i++)
#pragma unroll
        for (int j = 0; j < 4; j++) wmma::fill_fragment(acc[i][j], 0.0f);

    for (int kc = 0; kc < 4; kc++) {
        __syncthreads();
        // load x chunk [128 rows][32 cols] as float4
#pragma unroll
        for (int i = 0; i < 4; i++) {
            int f = tid + i * 256;              // float4 index over 128*8
            int row = f >> 3, c4 = f & 7;
            float4 v = make_float4(0.f, 0.f, 0.f, 0.f);
            if (n0 + row < N_NODES)
                v = reinterpret_cast<const float4*>(x)[(n0 + row) * 32 + kc * 8 + c4];
            *reinterpret_cast<float4*>(&xs[row * LDA + c4 * 4]) = v;
        }
        // load W chunk [32 k][128 j] as float4
#pragma unroll
        for (int i = 0; i < 4; i++) {
            int f = tid + i * 256;              // float4 index over 32*32
            int row = f >> 5, c4 = f & 31;
            *reinterpret_cast<float4*>(&ws[row * LDB + c4 * 4]) =
                reinterpret_cast<const float4*>(W)[(kc * 32 + row) * 32 + c4];
        }
        __syncthreads();

#pragma unroll
        for (int kk = 0; kk < 4; kk++) {
            wmma::fragment<wmma::matrix_a, 16, 16, 8, wmma::precision::tf32, wmma::row_major> a[2];
            wmma::fragment<wmma::matrix_b, 16, 16, 8, wmma::precision::tf32, wmma::row_major> b[4];
#pragma unroll
            for (int i = 0; i < 2; i++) {
                wmma::load_matrix_sync(a[i], &xs[(wr * 32 + i * 16) * LDA + kk * 8], LDA);
#pragma unroll
                for (int t = 0; t < a[i].num_elements; t++)
                    a[i].x[t] = wmma::__float_to_tf32(a[i].x[t]);
            }
#pragma unroll
            for (int j = 0; j < 4; j++) {
                wmma::load_matrix_sync(b[j], &ws[(kk * 8) * LDB + wc * 64 + j * 16], LDB);
#pragma unroll
                for (int t = 0; t < b[j].num_elements; t++)
                    b[j].x[t] = wmma::__float_to_tf32(b[j].x[t]);
            }
#pragma unroll
            for (int i = 0; i < 2; i++)
#pragma unroll
                for (int j = 0; j < 4; j++)
                    wmma::mma_sync(acc[i][j], a[i], b[j], acc[i][j]);
        }
    }

    __syncthreads();
#pragma unroll
    for (int i = 0; i < 2; i++)
#pragma unroll
        for (int j = 0; j < 4; j++)
            wmma::store_matrix_sync(&cs[(wr * 32 + i * 16) * LDC_S + wc * 64 + j * 16],
                                    acc[i][j], LDC_S, wmma::mem_row_major);
    __syncthreads();

    // epilogue: warp handles 16 rows; lane covers 4 cols (lane*4 .. lane*4+3)
    float4 b4 = make_float4(0.f, 0.f, 0.f, 0.f);
    float4 as4 = b4, ad4 = b4;
    if (is_gat) {
        as4 = *reinterpret_cast<const float4*>(&att_src[lane * 4]);
        ad4 = *reinterpret_cast<const float4*>(&att_dst[lane * 4]);
    } else {
        b4 = *reinterpret_cast<const float4*>(&lin_b[lane * 4]);
    }
    const int h = lane >> 3;     // head of this lane's columns
#pragma unroll
    for (int r = 0; r < 16; r++) {
        int row = wid * 16 + r;
        int n = n0 + row;
        float4 v = *reinterpret_cast<const float4*>(&cs[row * LDC_S + lane * 4]);
        if (!is_gat) {
            if (n < N_NODES) {
                v.x += b4.x; v.y += b4.y; v.z += b4.z; v.w += b4.w;
                *reinterpret_cast<float4*>(&g_hin[n * 128 + lane * 4]) = v;
            }
        } else {
            // logits from fp32 values (before fp16 conversion)
            float s = v.x * as4.x + v.y * as4.y + v.z * as4.z + v.w * as4.w;
            float d = v.x * ad4.x + v.y * ad4.y + v.z * ad4.z + v.w * ad4.w;
#pragma unroll
            for (int o = 4; o > 0; o >>= 1) {      // reduce within 8-lane head group
                s += __shfl_xor_sync(0xffffffffu, s, o);
                d += __shfl_xor_sync(0xffffffffu, d, o);
            }
            if (n < N_NODES) {
                __half2 h0 = __floats2half2_rn(v.x, v.y);
                __half2 h1 = __floats2half2_rn(v.z, v.w);
                uint2 p;
                p.x = *reinterpret_cast<uint32_t*>(&h0);
                p.y = *reinterpret_cast<uint32_t*>(&h1);
                reinterpret_cast<uint2*>(g_xp)[n * 32 + lane] = p;  // 8B per lane
                if ((lane & 7) == 0) {
                    g_asrc[n * 4 + h] = s;
                    g_adst[n * 4 + h] = d;
                }
            }
        }
    }
}

// ---------------- K3: degree histogram ----------------
__global__ void count_kernel(const int* __restrict__ ei) {
    int i = blockIdx.x * blockDim.x + threadIdx.x;
    if (i >= M_EDGES) return;
    int d = (i < E_EDGES) ? ei[E_EDGES + i] : (i - E_EDGES);
    atomicAdd(&g_cnt[d], 1);
}

// ---------------- K4-K6: exclusive scan ----------------
__global__ void scanA_kernel() {
    __shared__ int sh[256];
    int t = threadIdx.x;
    int base = blockIdx.x * 1024 + t * 4;
    int v0 = 0, v1 = 0, v2 = 0, v3 = 0;
    if (base + 0 < N_NODES) v0 = g_cnt[base + 0];
    if (base + 1 < N_NODES) v1 = g_cnt[base + 1];
    if (base + 2 < N_NODES) v2 = g_cnt[base + 2];
    if (base + 3 < N_NODES) v3 = g_cnt[base + 3];
    int s = v0 + v1 + v2 + v3;
    sh[t] = s; __syncthreads();
    for (int off = 1; off < 256; off <<= 1) {
        int u = (t >= off) ? sh[t - off] : 0; __syncthreads();
        sh[t] += u; __syncthreads();
    }
    int run = sh[t] - s;
    if (base + 0 < N_NODES) g_rowstart[base + 0] = run; run += v0;
    if (base + 1 < N_NODES) g_rowstart[base + 1] = run; run += v1;
    if (base + 2 < N_NODES) g_rowstart[base + 2] = run; run += v2;
    if (base + 3 < N_NODES) g_rowstart[base + 3] = run;
    if (t == 255) g_blksum[blockIdx.x] = sh[255];
}

__global__ void scanB_kernel(int nb) {
    __shared__ int sh[256];
    int t = threadIdx.x;
    int v = (t < nb) ? g_blksum[t] : 0;
    sh[t] = v; __syncthreads();
    for (int off = 1; off < 256; off <<= 1) {
        int u = (t >= off) ? sh[t - off] : 0; __syncthreads();
        sh[t] += u; __syncthreads();
    }
    if (t < nb) g_blkoff[t] = sh[t] - v;
}

__global__ void scanC_kernel() {
    int t = threadIdx.x;
    int off = g_blkoff[blockIdx.x];
#pragma unroll
    for (int j = 0; j < 4; j++) {
        int i = blockIdx.x * 1024 + t * 4 + j;
        if (i < N_NODES) {
            int r = g_rowstart[i] + off;
            g_rowstart[i] = r;
            g_cursor[i] = r;
        }
    }
}

// ---------------- K7: scatter edges into CSR ----------------
__global__ void scatter_kernel(const int* __restrict__ ei) {
    int i = blockIdx.x * blockDim.x + threadIdx.x;
    if (i >= M_EDGES) return;
    int s, d;
    if (i < E_EDGES) { s = ei[i]; d = ei[E_EDGES + i]; }
    else             { s = d = i - E_EDGES; }
    int pos = atomicAdd(&g_cursor[d], 1);
    g_csr[pos] = s;
}

// ---------------- K8: single-pass softmax + aggregation + fused BN column stats ----------------
// acc = sum_e w_e * xp[src_e], den = sum_e w_e, out = acc/den + bias (identical math to
// two-pass softmax). Then block-reduces column sums/sumsq into smem and REDG-adds to
// g_colsum/g_colsumsq, replacing the separate colstats pass over `out`.
__global__ __launch_bounds__(256) void agg_kernel(const float* __restrict__ gat_bias,
                                                  float* __restrict__ out) {
    __shared__ float ssum[128];
    __shared__ float ssq[128];
    int tid = threadIdx.x;
    int n = (blockIdx.x * blockDim.x + tid) >> 5;
    int lane = tid & 31;
    if (tid < 128) { ssum[tid] = 0.f; ssq[tid] = 0.f; }
    __syncthreads();

    float4 acc = make_float4(0.f, 0.f, 0.f, 0.f);
    bool active = (n < N_NODES);
    if (active) {
        int rs = g_rowstart[n];
        int deg = g_cnt[n];
        int h = lane >> 3;
        float ad_h = g_adst[n * 4 + h];
        const uint2* xp2 = reinterpret_cast<const uint2*>(g_xp);

        float den = 0.f;
        int e = rs, end = rs + deg;
        for (; e + 4 <= end; e += 4) {
            int s0 = g_csr[e], s1 = g_csr[e + 1], s2 = g_csr[e + 2], s3 = g_csr[e + 3];
            float a0 = g_asrc[s0 * 4 + h], a1 = g_asrc[s1 * 4 + h];
            float a2 = g_asrc[s2 * 4 + h], a3 = g_asrc[s3 * 4 + h];
            uint2 p0 = xp2[s0 * 32 + lane];
            uint2 p1 = xp2[s1 * 32 + lane];
            uint2 p2 = xp2[s2 * 32 + lane];
            uint2 p3 = xp2[s3 * 32 + lane];
            float w0 = __expf(lrelu02(a0 + ad_h));
            float w1 = __expf(lrelu02(a1 + ad_h));
            float w2 = __expf(lrelu02(a2 + ad_h));
            float w3 = __expf(lrelu02(a3 + ad_h));
            den += (w0 + w1) + (w2 + w3);
            float2 l0 = __half22float2(*reinterpret_cast<__half2*>(&p0.x));
            float2 m0 = __half22float2(*reinterpret_cast<__half2*>(&p0.y));
            float2 l1 = __half22float2(*reinterpret_cast<__half2*>(&p1.x));
            float2 m1 = __half22float2(*reinterpret_cast<__half2*>(&p1.y));
            float2 l2 = __half22float2(*reinterpret_cast<__half2*>(&p2.x));
            float2 m2 = __half22float2(*reinterpret_cast<__half2*>(&p2.y));
            float2 l3 = __half22float2(*reinterpret_cast<__half2*>(&p3.x));
            float2 m3 = __half22float2(*reinterpret_cast<__half2*>(&p3.y));
            acc.x += w0 * l0.x + w1 * l1.x + w2 * l2.x + w3 * l3.x;
            acc.y += w0 * l0.y + w1 * l1.y + w2 * l2.y + w3 * l3.y;
            acc.z += w0 * m0.x + w1 * m1.x + w2 * m2.x + w3 * m3.x;
            acc.w += w0 * m0.y + w1 * m1.y + w2 * m2.y + w3 * m3.y;
        }
        for (; e < end; e++) {
            int s = g_csr[e];
            float w = __expf(lrelu02(g_asrc[s * 4 + h] + ad_h));
            uint2 p = xp2[s * 32 + lane];
            float2 l = __half22float2(*reinterpret_cast<__half2*>(&p.x));
            float2 m = __half22float2(*reinterpret_cast<__half2*>(&p.y));
            den += w;
            acc.x += w * l.x; acc.y += w * l.y;
            acc.z += w * m.x; acc.w += w * m.y;
        }
        float inv = 1.0f / den;                    // den > 0 guaranteed by self loop
        float4 b = reinterpret_cast<const float4*>(gat_bias)[lane];
        acc.x = acc.x * inv + b.x; acc.y = acc.y * inv + b.y;
        acc.z = acc.z * inv + b.z; acc.w = acc.w * inv + b.w;
        reinterpret_cast<float4*>(out)[n * 32 + lane] = acc;

        // accumulate column statistics into smem
        atomicAdd(&ssum[lane * 4 + 0], acc.x);
        atomicAdd(&ssum[lane * 4 + 1], acc.y);
        atomicAdd(&ssum[lane * 4 + 2], acc.z);
        atomicAdd(&ssum[lane * 4 + 3], acc.w);
        atomicAdd(&ssq[lane * 4 + 0], acc.x * acc.x);
        atomicAdd(&ssq[lane * 4 + 1], acc.y * acc.y);
        atomicAdd(&ssq[lane * 4 + 2], acc.z * acc.z);
        atomicAdd(&ssq[lane * 4 + 3], acc.w * acc.w);
    }
    __syncthreads();
    if (tid < 128) {
        atomicAdd(&g_colsum[tid], ssum[tid]);
        atomicAdd(&g_colsumsq[tid], ssq[tid]);
    }
}

// ---------------- K10: BN + ELU + residual ----------------
__global__ void final_kernel(float* __restrict__ out,
                             const float* __restrict__ gamma, const float* __restrict__ beta) {
    int i = blockIdx.x * blockDim.x + threadIdx.x;
    if (i >= N_NODES * 128) return;
    int c = i & 127;
    const float invN = 1.0f / (float)N_NODES;
    float mu = g_colsum[c] * invN;
    float var = g_colsumsq[c] * invN - mu * mu;
    float y = out[i];
    float t = (y - mu) * rsqrtf(var + 1e-5f) * gamma[c] + beta[c];
    float h = t > 0.f ? t : expm1f(t);
    out[i] = g_hin[i] + h;
}

// ---------------- launch: forked graph (gemm || edge-CSR pipeline) ----------------
extern "C" void kernel_launch(void* const* d_in, const int* in_sizes, int n_in,
                              void* d_out, int out_size) {
    const float* x        = (const float*)d_in[0];
    const int*   ei       = (const int*)  d_in[1];
    const float* lin_w    = (const float*)d_in[2];
    const float* lin_b    = (const float*)d_in[3];
    const float* gat_w    = (const float*)d_in[4];
    const float* att_src  = (const float*)d_in[5];
    const float* att_dst  = (const float*)d_in[6];
    const float* gat_bias = (const float*)d_in[7];
    const float* bn_gamma = (const float*)d_in[8];
    const float* bn_beta  = (const float*)d_in[9];
    float* out = (float*)d_out;

    cudaFuncSetAttribute(gemm_kernel, cudaFuncAttributeMaxDynamicSharedMemorySize, GEMM_SMEM);

    const int NB = (N_NODES + 1023) / 1024;

    // host-side objects: created during the (single) capture call only; replays
    // execute the captured graph, not this host code.
    cudaStream_t sB;
    cudaStreamCreateWithFlags(&sB, cudaStreamNonBlocking);
    cudaEvent_t evFork, evJoin;
    cudaEventCreateWithFlags(&evFork, cudaEventDisableTiming);
    cudaEventCreateWithFlags(&evJoin, cudaEventDisableTiming);

    // fork: edge pipeline branch (independent of gemm)
    cudaEventRecord(evFork, 0);
    cudaStreamWaitEvent(sB, evFork, 0);

    // main branch: dense GEMM (+ logits)
    gemm_kernel<<<dim3((N_NODES + 127) / 128, 2), 256, GEMM_SMEM, 0>>>(
        x, lin_w, lin_b, gat_w, att_src, att_dst);

    // edge branch: init -> histogram -> scan -> scatter (CSR build)
    init_kernel<<<(N_NODES + 255) / 256, 256, 0, sB>>>();
    count_kernel<<<(M_EDGES + 255) / 256, 256, 0, sB>>>(ei);
    scanA_kernel<<<NB, 256, 0, sB>>>();
    scanB_kernel<<<1, 256, 0, sB>>>(NB);
    scanC_kernel<<<NB, 256, 0, sB>>>();
    scatter_kernel<<<(M_EDGES + 255) / 256, 256, 0, sB>>>(ei);

    // join
    cudaEventRecord(evJoin, sB);
    cudaStreamWaitEvent(0, evJoin, 0);

    agg_kernel<<<(N_NODES + 7) / 8, 256, 0, 0>>>(gat_bias, out);
    final_kernel<<<(N_NODES * 128 + 255) / 256, 256, 0, 0>>>(out, bn_gamma, bn_beta);
}

// round 12
// speedup vs baseline: 1.7940x; 1.3379x over previous
#include <cuda_runtime.h>
#include <cuda_bf16.h>
#include <cuda_fp16.h>
#include <mma.h>
#include <cstdint>

using namespace nvcuda;

// Problem constants
#define N_NODES  100000
#define E_EDGES  1600000
#define M_EDGES  (E_EDGES + N_NODES)   // 1,700,000 with self loops
#define IN_DIM   128
#define D_DIM    128
#define H_HEADS  4
#define C_CH     32

// ---------------- device scratch ----------------
__device__ float  g_hin[N_NODES * D_DIM];
__device__ __half g_xp [N_NODES * D_DIM];   // fp16 payload: only consumed by edge gather
__device__ float  g_asrc[N_NODES * H_HEADS];
__device__ float  g_adst[N_NODES * H_HEADS];
__device__ int    g_cnt[N_NODES];
__device__ int    g_rowstart[N_NODES];
__device__ int    g_cursor[N_NODES];
__device__ int    g_csr[M_EDGES];
__device__ int    g_blksum[256];
__device__ int    g_blkoff[256];
__device__ float  g_colsum[D_DIM];
__device__ float  g_colsumsq[D_DIM];

__device__ __forceinline__ float lrelu02(float v) { return v > 0.f ? v : 0.2f * v; }

// ---------------- K0: init (runs on edge branch; also zeroes BN accumulators) ----------------
__global__ void init_kernel() {
    int i = blockIdx.x * blockDim.x + threadIdx.x;
    if (i < N_NODES) g_cnt[i] = 0;
    if (i < D_DIM) { g_colsum[i] = 0.f; g_colsumsq[i] = 0.f; }
}

// ---------------- K1: wmma fp16 GEMM (fp32 accum) + fused attention logits ----------------
// grid = (ceil(N/128), 2): y=0 -> h_in = x@lin_w + lin_b ; y=1 -> xp(fp16) = x@gat_w, + logits.
// Block 256 thr (8 warps). BM=128, BN=128, full K=128 resident in smem as fp16.
// Warp tile 32x64 = 2x4 frags of m16n16k16; 8 k-steps, single sync mainloop.
#define LDH   136   // half stride (128 + 8)
#define LDC_S 132   // float stride for C staging (128 + 4)
#define XS_HALFS (128 * LDH)
#define GEMM_SMEM (2 * XS_HALFS * 2)   // xs + ws, fp16: 69632 B (cs float reuse = 67584 B)

__global__ __launch_bounds__(256) void gemm_kernel(
    const float* __restrict__ x, const float* __restrict__ lin_w,
    const float* __restrict__ lin_b, const float* __restrict__ gat_w,
    const float* __restrict__ att_src, const float* __restrict__ att_dst)
{
    extern __shared__ char smraw[];
    __half* xs = reinterpret_cast<__half*>(smraw);            // [128][LDH]
    __half* ws = xs + XS_HALFS;                               // [128][LDH]
    float*  cs = reinterpret_cast<float*>(smraw);             // [128][LDC_S] (epilogue reuse)

    const bool is_gat = (blockIdx.y != 0);
    const float* W = is_gat ? gat_w : lin_w;
    const int n0 = blockIdx.x * 128;
    const int tid = threadIdx.x, wid = tid >> 5, lane = tid & 31;
    const int wr = wid & 3;          // warp row group: rows wr*32..wr*32+31
    const int wc = wid >> 2;         // warp col group: cols wc*64..wc*64+63

    // load full x tile [128][128] fp32 -> fp16 smem
#pragma unroll
    for (int i = 0; i < 16; i++) {
        int f = tid + i * 256;               // float4 index over 128*32
        int row = f >> 5, c4 = f & 31;
        float4 v = make_float4(0.f, 0.f, 0.f, 0.f);
        if (n0 + row < N_NODES)
            v = reinterpret_cast<const float4*>(x)[(n0 + row) * 32 + c4];
        __half2 h0 = __floats2half2_rn(v.x, v.y);
        __half2 h1 = __floats2half2_rn(v.z, v.w);
        uint2 p;
        p.x = *reinterpret_cast<uint32_t*>(&h0);
        p.y = *reinterpret_cast<uint32_t*>(&h1);
        *reinterpret_cast<uint2*>(&xs[row * LDH + c4 * 4]) = p;
    }
    // load full W [128][128] fp32 -> fp16 smem
#pragma unroll
    for (int i = 0; i < 16; i++) {
        int f = tid + i * 256;
        int row = f >> 5, c4 = f & 31;
        float4 v = reinterpret_cast<const float4*>(W)[row * 32 + c4];
        __half2 h0 = __floats2half2_rn(v.x, v.y);
        __half2 h1 = __floats2half2_rn(v.z, v.w);
        uint2 p;
        p.x = *reinterpret_cast<uint32_t*>(&h0);
        p.y = *reinterpret_cast<uint32_t*>(&h1);
        *reinterpret_cast<uint2*>(&ws[row * LDH + c4 * 4]) = p;
    }
    __syncthreads();

    wmma::fragment<wmma::accumulator, 16, 16, 16, float> acc[2][4];
#pragma unroll
    for (int i = 0; i < 2; i++)
#pragma unroll
        for (int j = 0; j < 4; j++) wmma::fill_fragment(acc[i][j], 0.0f);

#pragma unroll
    for (int k = 0; k < 8; k++) {        // 8 k-steps of 16
        wmma::fragment<wmma::matrix_a, 16, 16, 16, __half, wmma::row_major> a[2];
        wmma::fragment<wmma::matrix_b, 16, 16, 16, __half, wmma::row_major> b[4];
#pragma unroll
        for (int i = 0; i < 2; i++)
            wmma::load_matrix_sync(a[i], &xs[(wr * 32 + i * 16) * LDH + k * 16], LDH);
#pragma unroll
        for (int j = 0; j < 4; j++)
            wmma::load_matrix_sync(b[j], &ws[(k * 16) * LDH + wc * 64 + j * 16], LDH);
#pragma unroll
        for (int i = 0; i < 2; i++)
#pragma unroll
            for (int j = 0; j < 4; j++)
                wmma::mma_sync(acc[i][j], a[i], b[j], acc[i][j]);
    }

    __syncthreads();                      // done with xs/ws; reuse as float C staging
#pragma unroll
    for (int i = 0; i < 2; i++)
#pragma unroll
        for (int j = 0; j < 4; j++)
            wmma::store_matrix_sync(&cs[(wr * 32 + i * 16) * LDC_S + wc * 64 + j * 16],
                                    acc[i][j], LDC_S, wmma::mem_row_major);
    __syncthreads();

    // epilogue: warp handles 16 rows; lane covers 4 cols (lane*4 .. lane*4+3)
    float4 b4 = make_float4(0.f, 0.f, 0.f, 0.f);
    float4 as4 = b4, ad4 = b4;
    if (is_gat) {
        as4 = *reinterpret_cast<const float4*>(&att_src[lane * 4]);
        ad4 = *reinterpret_cast<const float4*>(&att_dst[lane * 4]);
    } else {
        b4 = *reinterpret_cast<const float4*>(&lin_b[lane * 4]);
    }
    const int h = lane >> 3;     // head of this lane's columns
#pragma unroll
    for (int r = 0; r < 16; r++) {
        int row = wid * 16 + r;
        int n = n0 + row;
        float4 v = *reinterpret_cast<const float4*>(&cs[row * LDC_S + lane * 4]);
        if (!is_gat) {
            if (n < N_NODES) {
                v.x += b4.x; v.y += b4.y; v.z += b4.z; v.w += b4.w;
                *reinterpret_cast<float4*>(&g_hin[n * 128 + lane * 4]) = v;
            }
        } else {
            // logits from fp32 accumulators (before fp16 conversion)
            float s = v.x * as4.x + v.y * as4.y + v.z * as4.z + v.w * as4.w;
            float d = v.x * ad4.x + v.y * ad4.y + v.z * ad4.z + v.w * ad4.w;
#pragma unroll
            for (int o = 4; o > 0; o >>= 1) {      // reduce within 8-lane head group
                s += __shfl_xor_sync(0xffffffffu, s, o);
                d += __shfl_xor_sync(0xffffffffu, d, o);
            }
            if (n < N_NODES) {
                __half2 h0 = __floats2half2_rn(v.x, v.y);
                __half2 h1 = __floats2half2_rn(v.z, v.w);
                uint2 p;
                p.x = *reinterpret_cast<uint32_t*>(&h0);
                p.y = *reinterpret_cast<uint32_t*>(&h1);
                reinterpret_cast<uint2*>(g_xp)[n * 32 + lane] = p;  // 8B per lane
                if ((lane & 7) == 0) {
                    g_asrc[n * 4 + h] = s;
                    g_adst[n * 4 + h] = d;
                }
            }
        }
    }
}

// ---------------- K3: degree histogram ----------------
__global__ void count_kernel(const int* __restrict__ ei) {
    int i = blockIdx.x * blockDim.x + threadIdx.x;
    if (i >= M_EDGES) return;
    int d = (i < E_EDGES) ? ei[E_EDGES + i] : (i - E_EDGES);
    atomicAdd(&g_cnt[d], 1);
}

// ---------------- K4-K6: exclusive scan ----------------
__global__ void scanA_kernel() {
    __shared__ int sh[256];
    int t = threadIdx.x;
    int base = blockIdx.x * 1024 + t * 4;
    int v0 = 0, v1 = 0, v2 = 0, v3 = 0;
    if (base + 0 < N_NODES) v0 = g_cnt[base + 0];
    if (base + 1 < N_NODES) v1 = g_cnt[base + 1];
    if (base + 2 < N_NODES) v2 = g_cnt[base + 2];
    if (base + 3 < N_NODES) v3 = g_cnt[base + 3];
    int s = v0 + v1 + v2 + v3;
    sh[t] = s; __syncthreads();
    for (int off = 1; off < 256; off <<= 1) {
        int u = (t >= off) ? sh[t - off] : 0; __syncthreads();
        sh[t] += u; __syncthreads();
    }
    int run = sh[t] - s;
    if (base + 0 < N_NODES) g_rowstart[base + 0] = run; run += v0;
    if (base + 1 < N_NODES) g_rowstart[base + 1] = run; run += v1;
    if (base + 2 < N_NODES) g_rowstart[base + 2] = run; run += v2;
    if (base + 3 < N_NODES) g_rowstart[base + 3] = run;
    if (t == 255) g_blksum[blockIdx.x] = sh[255];
}

__global__ void scanB_kernel(int nb) {
    __shared__ int sh[256];
    int t = threadIdx.x;
    int v = (t < nb) ? g_blksum[t] : 0;
    sh[t] = v; __syncthreads();
    for (int off = 1; off < 256; off <<= 1) {
        int u = (t >= off) ? sh[t - off] : 0; __syncthreads();
        sh[t] += u; __syncthreads();
    }
    if (t < nb) g_blkoff[t] = sh[t] - v;
}

__global__ void scanC_kernel() {
    int t = threadIdx.x;
    int off = g_blkoff[blockIdx.x];
#pragma unroll
    for (int j = 0; j < 4; j++) {
        int i = blockIdx.x * 1024 + t * 4 + j;
        if (i < N_NODES) {
            int r = g_rowstart[i] + off;
            g_rowstart[i] = r;
            g_cursor[i] = r;
        }
    }
}

// ---------------- K7: scatter edges into CSR ----------------
__global__ void scatter_kernel(const int* __restrict__ ei) {
    int i = blockIdx.x * blockDim.x + threadIdx.x;
    if (i >= M_EDGES) return;
    int s, d;
    if (i < E_EDGES) { s = ei[i]; d = ei[E_EDGES + i]; }
    else             { s = d = i - E_EDGES; }
    int pos = atomicAdd(&g_cursor[d], 1);
    g_csr[pos] = s;
}

// ---------------- K8: single-pass softmax + aggregation + fused BN column stats ----------------
__global__ __launch_bounds__(256) void agg_kernel(const float* __restrict__ gat_bias,
                                                  float* __restrict__ out) {
    __shared__ float ssum[128];
    __shared__ float ssq[128];
    int tid = threadIdx.x;
    int n = (blockIdx.x * blockDim.x + tid) >> 5;
    int lane = tid & 31;
    if (tid < 128) { ssum[tid] = 0.f; ssq[tid] = 0.f; }
    __syncthreads();

    float4 acc = make_float4(0.f, 0.f, 0.f, 0.f);
    bool active = (n < N_NODES);
    if (active) {
        int rs = g_rowstart[n];
        int deg = g_cnt[n];
        int h = lane >> 3;
        float ad_h = g_adst[n * 4 + h];
        const uint2* xp2 = reinterpret_cast<const uint2*>(g_xp);

        float den = 0.f;
        int e = rs, end = rs + deg;
        for (; e + 4 <= end; e += 4) {
            int s0 = g_csr[e], s1 = g_csr[e + 1], s2 = g_csr[e + 2], s3 = g_csr[e + 3];
            float a0 = g_asrc[s0 * 4 + h], a1 = g_asrc[s1 * 4 + h];
            float a2 = g_asrc[s2 * 4 + h], a3 = g_asrc[s3 * 4 + h];
            uint2 p0 = xp2[s0 * 32 + lane];
            uint2 p1 = xp2[s1 * 32 + lane];
            uint2 p2 = xp2[s2 * 32 + lane];
            uint2 p3 = xp2[s3 * 32 + lane];
            float w0 = __expf(lrelu02(a0 + ad_h));
            float w1 = __expf(lrelu02(a1 + ad_h));
            float w2 = __expf(lrelu02(a2 + ad_h));
            float w3 = __expf(lrelu02(a3 + ad_h));
            den += (w0 + w1) + (w2 + w3);
            float2 l0 = __half22float2(*reinterpret_cast<__half2*>(&p0.x));
            float2 m0 = __half22float2(*reinterpret_cast<__half2*>(&p0.y));
            float2 l1 = __half22float2(*reinterpret_cast<__half2*>(&p1.x));
            float2 m1 = __half22float2(*reinterpret_cast<__half2*>(&p1.y));
            float2 l2 = __half22float2(*reinterpret_cast<__half2*>(&p2.x));
            float2 m2 = __half22float2(*reinterpret_cast<__half2*>(&p2.y));
            float2 l3 = __half22float2(*reinterpret_cast<__half2*>(&p3.x));
            float2 m3 = __half22float2(*reinterpret_cast<__half2*>(&p3.y));
            acc.x += w0 * l0.x + w1 * l1.x + w2 * l2.x + w3 * l3.x;
            acc.y += w0 * l0.y + w1 * l1.y + w2 * l2.y + w3 * l3.y;
            acc.z += w0 * m0.x + w1 * m1.x + w2 * m2.x + w3 * m3.x;
            acc.w += w0 * m0.y + w1 * m1.y + w2 * m2.y + w3 * m3.y;
        }
        for (; e < end; e++) {
            int s = g_csr[e];
            float w = __expf(lrelu02(g_asrc[s * 4 + h] + ad_h));
            uint2 p = xp2[s * 32 + lane];
            float2 l = __half22float2(*reinterpret_cast<__half2*>(&p.x));
            float2 m = __half22float2(*reinterpret_cast<__half2*>(&p.y));
            den += w;
            acc.x += w * l.x; acc.y += w * l.y;
            acc.z += w * m.x; acc.w += w * m.y;
        }
        float inv = 1.0f / den;                    // den > 0 guaranteed by self loop
        float4 b = reinterpret_cast<const float4*>(gat_bias)[lane];
        acc.x = acc.x * inv + b.x; acc.y = acc.y * inv + b.y;
        acc.z = acc.z * inv + b.z; acc.w = acc.w * inv + b.w;
        reinterpret_cast<float4*>(out)[n * 32 + lane] = acc;

        atomicAdd(&ssum[lane * 4 + 0], acc.x);
        atomicAdd(&ssum[lane * 4 + 1], acc.y);
        atomicAdd(&ssum[lane * 4 + 2], acc.z);
        atomicAdd(&ssum[lane * 4 + 3], acc.w);
        atomicAdd(&ssq[lane * 4 + 0], acc.x * acc.x);
        atomicAdd(&ssq[lane * 4 + 1], acc.y * acc.y);
        atomicAdd(&ssq[lane * 4 + 2], acc.z * acc.z);
        atomicAdd(&ssq[lane * 4 + 3], acc.w * acc.w);
    }
    __syncthreads();
    if (tid < 128) {
        atomicAdd(&g_colsum[tid], ssum[tid]);
        atomicAdd(&g_colsumsq[tid], ssq[tid]);
    }
}

// ---------------- K10: BN + ELU + residual ----------------
__global__ void final_kernel(float* __restrict__ out,
                             const float* __restrict__ gamma, const float* __restrict__ beta) {
    int i = blockIdx.x * blockDim.x + threadIdx.x;
    if (i >= N_NODES * 128) return;
    int c = i & 127;
    const float invN = 1.0f / (float)N_NODES;
    float mu = g_colsum[c] * invN;
    float var = g_colsumsq[c] * invN - mu * mu;
    float y = out[i];
    float t = (y - mu) * rsqrtf(var + 1e-5f) * gamma[c] + beta[c];
    float h = t > 0.f ? t : expm1f(t);
    out[i] = g_hin[i] + h;
}

// ---------------- launch: forked graph (gemm || edge-CSR pipeline) ----------------
extern "C" void kernel_launch(void* const* d_in, const int* in_sizes, int n_in,
                              void* d_out, int out_size) {
    const float* x        = (const float*)d_in[0];
    const int*   ei       = (const int*)  d_in[1];
    const float* lin_w    = (const float*)d_in[2];
    const float* lin_b    = (const float*)d_in[3];
    const float* gat_w    = (const float*)d_in[4];
    const float* att_src  = (const float*)d_in[5];
    const float* att_dst  = (const float*)d_in[6];
    const float* gat_bias = (const float*)d_in[7];
    const float* bn_gamma = (const float*)d_in[8];
    const float* bn_beta  = (const float*)d_in[9];
    float* out = (float*)d_out;

    cudaFuncSetAttribute(gemm_kernel, cudaFuncAttributeMaxDynamicSharedMemorySize, GEMM_SMEM);

    const int NB = (N_NODES + 1023) / 1024;

    // host-side objects: created during the (single) capture call only; replays
    // execute the captured graph, not this host code.
    cudaStream_t sB;
    cudaStreamCreateWithFlags(&sB, cudaStreamNonBlocking);
    cudaEvent_t evFork, evJoin;
    cudaEventCreateWithFlags(&evFork, cudaEventDisableTiming);
    cudaEventCreateWithFlags(&evJoin, cudaEventDisableTiming);

    // fork: edge pipeline branch (independent of gemm)
    cudaEventRecord(evFork, 0);
    cudaStreamWaitEvent(sB, evFork, 0);

    // main branch: dense GEMM (+ logits)
    gemm_kernel<<<dim3((N_NODES + 127) / 128, 2), 256, GEMM_SMEM, 0>>>(
        x, lin_w, lin_b, gat_w, att_src, att_dst);

    // edge branch: init -> histogram -> scan -> scatter (CSR build)
    init_kernel<<<(N_NODES + 255) / 256, 256, 0, sB>>>();
    count_kernel<<<(M_EDGES + 255) / 256, 256, 0, sB>>>(ei);
    scanA_kernel<<<NB, 256, 0, sB>>>();
    scanB_kernel<<<1, 256, 0, sB>>>(NB);
    scanC_kernel<<<NB, 256, 0, sB>>>();
    scatter_kernel<<<(M_EDGES + 255) / 256, 256, 0, sB>>>(ei);

    // join
    cudaEventRecord(evJoin, sB);
    cudaStreamWaitEvent(0, evJoin, 0);

    agg_kernel<<<(N_NODES + 7) / 8, 256, 0, 0>>>(gat_bias, out);
    final_kernel<<<(N_NODES * 128 + 255) / 256, 256, 0, 0>>>(out, bn_gamma, bn_beta);
}

// round 16
// speedup vs baseline: 1.8937x; 1.0556x over previous
#include <cuda_runtime.h>
#include <cuda_bf16.h>
#include <cuda_fp16.h>
#include <mma.h>
#include <cstdint>

using namespace nvcuda;

// Problem constants
#define N_NODES  100000
#define E_EDGES  1600000
#define M_EDGES  (E_EDGES + N_NODES)   // 1,700,000 with self loops
#define IN_DIM   128
#define D_DIM    128
#define H_HEADS  4
#define C_CH     32

// ---------------- device scratch ----------------
__device__ float  g_hin[N_NODES * D_DIM];
__device__ __half g_xp [N_NODES * D_DIM];   // fp16 payload: only consumed by edge gather
__device__ float  g_asrc[N_NODES * H_HEADS];
__device__ float  g_adst[N_NODES * H_HEADS];
__device__ int    g_cnt[N_NODES];
__device__ int    g_rowstart[N_NODES];
__device__ int    g_cursor[N_NODES];
__device__ int    g_csr[M_EDGES];
__device__ int    g_blksum[256];
__device__ int    g_blkoff[256];
__device__ float  g_colsum[D_DIM];
__device__ float  g_colsumsq[D_DIM];

__device__ __forceinline__ float lrelu02(float v) { return v > 0.f ? v : 0.2f * v; }

// ---------------- K0: init (runs on edge branch; also zeroes BN accumulators) ----------------
__global__ void init_kernel() {
    int i = blockIdx.x * blockDim.x + threadIdx.x;
    if (i < N_NODES) g_cnt[i] = 0;
    if (i < D_DIM) { g_colsum[i] = 0.f; g_colsumsq[i] = 0.f; }
}

// ---------------- K1: wmma fp16 GEMM (fp32 accum) + fused attention logits ----------------
// grid = (ceil(N/64), 2): y=0 -> h_in = x@lin_w + lin_b ; y=1 -> xp(fp16) = x@gat_w, + logits.
// Block 256 thr (8 warps). BM=64, BN=128, full K=128 resident in smem as fp16.
// Warp tile 32x32 = 2x2 frags of m16n16k16; smem 52.2KB -> 3-4 blocks/SM resident.
#define LDH   136   // half stride (128 + 8)
#define LDC_S 132   // float stride for C staging (64 rows)
#define XS_HALFS (64 * LDH)
#define WS_HALFS (128 * LDH)
#define GEMM_SMEM ((XS_HALFS + WS_HALFS) * 2)   // 52224 B (cs float reuse = 33792 B)

__global__ __launch_bounds__(256) void gemm_kernel(
    const float* __restrict__ x, const float* __restrict__ lin_w,
    const float* __restrict__ lin_b, const float* __restrict__ gat_w,
    const float* __restrict__ att_src, const float* __restrict__ att_dst)
{
    extern __shared__ char smraw[];
    __half* xs = reinterpret_cast<__half*>(smraw);            // [64][LDH]
    __half* ws = xs + XS_HALFS;                               // [128][LDH]
    float*  cs = reinterpret_cast<float*>(smraw);             // [64][LDC_S] (epilogue reuse)

    const bool is_gat = (blockIdx.y != 0);
    const float* W = is_gat ? gat_w : lin_w;
    const int n0 = blockIdx.x * 64;
    const int tid = threadIdx.x, wid = tid >> 5, lane = tid & 31;
    const int wr = wid & 1;          // warp row group: rows wr*32..wr*32+31
    const int wc = wid >> 1;         // warp col group: cols wc*32..wc*32+31

    // load x tile [64][128] fp32 -> fp16 smem
#pragma unroll
    for (int i = 0; i < 8; i++) {
        int f = tid + i * 256;               // float4 index over 64*32
        int row = f >> 5, c4 = f & 31;
        float4 v = make_float4(0.f, 0.f, 0.f, 0.f);
        if (n0 + row < N_NODES)
            v = reinterpret_cast<const float4*>(x)[(n0 + row) * 32 + c4];
        __half2 h0 = __floats2half2_rn(v.x, v.y);
        __half2 h1 = __floats2half2_rn(v.z, v.w);
        uint2 p;
        p.x = *reinterpret_cast<uint32_t*>(&h0);
        p.y = *reinterpret_cast<uint32_t*>(&h1);
        *reinterpret_cast<uint2*>(&xs[row * LDH + c4 * 4]) = p;
    }
    // load full W [128][128] fp32 -> fp16 smem (L2-resident after first blocks)
#pragma unroll
    for (int i = 0; i < 16; i++) {
        int f = tid + i * 256;
        int row = f >> 5, c4 = f & 31;
        float4 v = reinterpret_cast<const float4*>(W)[row * 32 + c4];
        __half2 h0 = __floats2half2_rn(v.x, v.y);
        __half2 h1 = __floats2half2_rn(v.z, v.w);
        uint2 p;
        p.x = *reinterpret_cast<uint32_t*>(&h0);
        p.y = *reinterpret_cast<uint32_t*>(&h1);
        *reinterpret_cast<uint2*>(&ws[row * LDH + c4 * 4]) = p;
    }
    __syncthreads();

    wmma::fragment<wmma::accumulator, 16, 16, 16, float> acc[2][2];
#pragma unroll
    for (int i = 0; i < 2; i++)
#pragma unroll
        for (int j = 0; j < 2; j++) wmma::fill_fragment(acc[i][j], 0.0f);

#pragma unroll
    for (int k = 0; k < 8; k++) {        // 8 k-steps of 16
        wmma::fragment<wmma::matrix_a, 16, 16, 16, __half, wmma::row_major> a[2];
        wmma::fragment<wmma::matrix_b, 16, 16, 16, __half, wmma::row_major> b[2];
#pragma unroll
        for (int i = 0; i < 2; i++)
            wmma::load_matrix_sync(a[i], &xs[(wr * 32 + i * 16) * LDH + k * 16], LDH);
#pragma unroll
        for (int j = 0; j < 2; j++)
            wmma::load_matrix_sync(b[j], &ws[(k * 16) * LDH + wc * 32 + j * 16], LDH);
#pragma unroll
        for (int i = 0; i < 2; i++)
#pragma unroll
            for (int j = 0; j < 2; j++)
                wmma::mma_sync(acc[i][j], a[i], b[j], acc[i][j]);
    }

    __syncthreads();                      // done with xs/ws; reuse as float C staging
#pragma unroll
    for (int i = 0; i < 2; i++)
#pragma unroll
        for (int j = 0; j < 2; j++)
            wmma::store_matrix_sync(&cs[(wr * 32 + i * 16) * LDC_S + wc * 32 + j * 16],
                                    acc[i][j], LDC_S, wmma::mem_row_major);
    __syncthreads();

    // epilogue: warp handles 8 rows; lane covers 4 cols (lane*4 .. lane*4+3)
    float4 b4 = make_float4(0.f, 0.f, 0.f, 0.f);
    float4 as4 = b4, ad4 = b4;
    if (is_gat) {
        as4 = *reinterpret_cast<const float4*>(&att_src[lane * 4]);
        ad4 = *reinterpret_cast<const float4*>(&att_dst[lane * 4]);
    } else {
        b4 = *reinterpret_cast<const float4*>(&lin_b[lane * 4]);
    }
    const int h = lane >> 3;     // head of this lane's columns
#pragma unroll
    for (int r = 0; r < 8; r++) {
        int row = wid * 8 + r;
        int n = n0 + row;
        float4 v = *reinterpret_cast<const float4*>(&cs[row * LDC_S + lane * 4]);
        if (!is_gat) {
            if (n < N_NODES) {
                v.x += b4.x; v.y += b4.y; v.z += b4.z; v.w += b4.w;
                *reinterpret_cast<float4*>(&g_hin[n * 128 + lane * 4]) = v;
            }
        } else {
            // logits from fp32 accumulators (before fp16 conversion)
            float s = v.x * as4.x + v.y * as4.y + v.z * as4.z + v.w * as4.w;
            float d = v.x * ad4.x + v.y * ad4.y + v.z * ad4.z + v.w * ad4.w;
#pragma unroll
            for (int o = 4; o > 0; o >>= 1) {      // reduce within 8-lane head group
                s += __shfl_xor_sync(0xffffffffu, s, o);
                d += __shfl_xor_sync(0xffffffffu, d, o);
            }
            if (n < N_NODES) {
                __half2 h0 = __floats2half2_rn(v.x, v.y);
                __half2 h1 = __floats2half2_rn(v.z, v.w);
                uint2 p;
                p.x = *reinterpret_cast<uint32_t*>(&h0);
                p.y = *reinterpret_cast<uint32_t*>(&h1);
                reinterpret_cast<uint2*>(g_xp)[n * 32 + lane] = p;  // 8B per lane
                if ((lane & 7) == 0) {
                    g_asrc[n * 4 + h] = s;
                    g_adst[n * 4 + h] = d;
                }
            }
        }
    }
}

// ---------------- K3: degree histogram ----------------
__global__ void count_kernel(const int* __restrict__ ei) {
    int i = blockIdx.x * blockDim.x + threadIdx.x;
    if (i >= M_EDGES) return;
    int d = (i < E_EDGES) ? ei[E_EDGES + i] : (i - E_EDGES);
    atomicAdd(&g_cnt[d], 1);
}

// ---------------- K4-K6: exclusive scan ----------------
__global__ void scanA_kernel() {
    __shared__ int sh[256];
    int t = threadIdx.x;
    int base = blockIdx.x * 1024 + t * 4;
    int v0 = 0, v1 = 0, v2 = 0, v3 = 0;
    if (base + 0 < N_NODES) v0 = g_cnt[base + 0];
    if (base + 1 < N_NODES) v1 = g_cnt[base + 1];
    if (base + 2 < N_NODES) v2 = g_cnt[base + 2];
    if (base + 3 < N_NODES) v3 = g_cnt[base + 3];
    int s = v0 + v1 + v2 + v3;
    sh[t] = s; __syncthreads();
    for (int off = 1; off < 256; off <<= 1) {
        int u = (t >= off) ? sh[t - off] : 0; __syncthreads();
        sh[t] += u; __syncthreads();
    }
    int run = sh[t] - s;
    if (base + 0 < N_NODES) g_rowstart[base + 0] = run; run += v0;
    if (base + 1 < N_NODES) g_rowstart[base + 1] = run; run += v1;
    if (base + 2 < N_NODES) g_rowstart[base + 2] = run; run += v2;
    if (base + 3 < N_NODES) g_rowstart[base + 3] = run;
    if (t == 255) g_blksum[blockIdx.x] = sh[255];
}

__global__ void scanB_kernel(int nb) {
    __shared__ int sh[256];
    int t = threadIdx.x;
    int v = (t < nb) ? g_blksum[t] : 0;
    sh[t] = v; __syncthreads();
    for (int off = 1; off < 256; off <<= 1) {
        int u = (t >= off) ? sh[t - off] : 0; __syncthreads();
        sh[t] += u; __syncthreads();
    }
    if (t < nb) g_blkoff[t] = sh[t] - v;
}

__global__ void scanC_kernel() {
    int t = threadIdx.x;
    int off = g_blkoff[blockIdx.x];
#pragma unroll
    for (int j = 0; j < 4; j++) {
        int i = blockIdx.x * 1024 + t * 4 + j;
        if (i < N_NODES) {
            int r = g_rowstart[i] + off;
            g_rowstart[i] = r;
            g_cursor[i] = r;
        }
    }
}

// ---------------- K7: scatter edges into CSR ----------------
__global__ void scatter_kernel(const int* __restrict__ ei) {
    int i = blockIdx.x * blockDim.x + threadIdx.x;
    if (i >= M_EDGES) return;
    int s, d;
    if (i < E_EDGES) { s = ei[i]; d = ei[E_EDGES + i]; }
    else             { s = d = i - E_EDGES; }
    int pos = atomicAdd(&g_cursor[d], 1);
    g_csr[pos] = s;
}

// ---------------- K8: single-pass softmax + aggregation + fused BN column stats ----------------
// acc = sum_e w_e * xp[src_e], den = sum_e w_e, out = acc/den + bias (identical math to
// two-pass softmax). CSR read as aligned int4 (4 edges per load), unroll 8 for MLP.
__global__ __launch_bounds__(256) void agg_kernel(const float* __restrict__ gat_bias,
                                                  float* __restrict__ out) {
    __shared__ float ssum[128];
    __shared__ float ssq[128];
    int tid = threadIdx.x;
    int n = (blockIdx.x * blockDim.x + tid) >> 5;
    int lane = tid & 31;
    if (tid < 128) { ssum[tid] = 0.f; ssq[tid] = 0.f; }
    __syncthreads();

    float4 acc = make_float4(0.f, 0.f, 0.f, 0.f);
    bool active = (n < N_NODES);
    if (active) {
        int rs = g_rowstart[n];
        int deg = g_cnt[n];
        int h = lane >> 3;
        float ad_h = g_adst[n * 4 + h];
        const uint2* xp2 = reinterpret_cast<const uint2*>(g_xp);
        float den = 0.f;

        auto do1 = [&](int s) {
            float w = __expf(lrelu02(g_asrc[s * 4 + h] + ad_h));
            uint2 p = xp2[s * 32 + lane];
            float2 l = __half22float2(*reinterpret_cast<__half2*>(&p.x));
            float2 m = __half22float2(*reinterpret_cast<__half2*>(&p.y));
            den += w;
            acc.x += w * l.x; acc.y += w * l.y;
            acc.z += w * m.x; acc.w += w * m.y;
        };
        auto do4 = [&](int4 q) {
            float a0 = g_asrc[q.x * 4 + h], a1 = g_asrc[q.y * 4 + h];
            float a2 = g_asrc[q.z * 4 + h], a3 = g_asrc[q.w * 4 + h];
            uint2 p0 = xp2[q.x * 32 + lane];
            uint2 p1 = xp2[q.y * 32 + lane];
            uint2 p2 = xp2[q.z * 32 + lane];
            uint2 p3 = xp2[q.w * 32 + lane];
            float w0 = __expf(lrelu02(a0 + ad_h));
            float w1 = __expf(lrelu02(a1 + ad_h));
            float w2 = __expf(lrelu02(a2 + ad_h));
            float w3 = __expf(lrelu02(a3 + ad_h));
            den += (w0 + w1) + (w2 + w3);
            float2 l0 = __half22float2(*reinterpret_cast<__half2*>(&p0.x));
            float2 m0 = __half22float2(*reinterpret_cast<__half2*>(&p0.y));
            float2 l1 = __half22float2(*reinterpret_cast<__half2*>(&p1.x));
            float2 m1 = __half22float2(*reinterpret_cast<__half2*>(&p1.y));
            float2 l2 = __half22float2(*reinterpret_cast<__half2*>(&p2.x));
            float2 m2 = __half22float2(*reinterpret_cast<__half2*>(&p2.y));
            float2 l3 = __half22float2(*reinterpret_cast<__half2*>(&p3.x));
            float2 m3 = __half22float2(*reinterpret_cast<__half2*>(&p3.y));
            acc.x += w0 * l0.x + w1 * l1.x + w2 * l2.x + w3 * l3.x;
            acc.y += w0 * l0.y + w1 * l1.y + w2 * l2.y + w3 * l3.y;
            acc.z += w0 * m0.x + w1 * m1.x + w2 * m2.x + w3 * m3.x;
            acc.w += w0 * m0.y + w1 * m1.y + w2 * m2.y + w3 * m3.y;
        };

        int e = rs, end = rs + deg;
        while (e < end && (e & 3)) { do1(g_csr[e]); e++; }      // align to 16B
        for (; e + 8 <= end; e += 8) {                           // unroll 8: 2x int4
            int4 qa = *reinterpret_cast<const int4*>(&g_csr[e]);
            int4 qb = *reinterpret_cast<const int4*>(&g_csr[e + 4]);
            do4(qa);
            do4(qb);
        }
        if (e + 4 <= end) {
            do4(*reinterpret_cast<const int4*>(&g_csr[e]));
            e += 4;
        }
        for (; e < end; e++) do1(g_csr[e]);

        float inv = 1.0f / den;                    // den > 0 guaranteed by self loop
        float4 b = reinterpret_cast<const float4*>(gat_bias)[lane];
        acc.x = acc.x * inv + b.x; acc.y = acc.y * inv + b.y;
        acc.z = acc.z * inv + b.z; acc.w = acc.w * inv + b.w;
        reinterpret_cast<float4*>(out)[n * 32 + lane] = acc;

        atomicAdd(&ssum[lane * 4 + 0], acc.x);
        atomicAdd(&ssum[lane * 4 + 1], acc.y);
        atomicAdd(&ssum[lane * 4 + 2], acc.z);
        atomicAdd(&ssum[lane * 4 + 3], acc.w);
        atomicAdd(&ssq[lane * 4 + 0], acc.x * acc.x);
        atomicAdd(&ssq[lane * 4 + 1], acc.y * acc.y);
        atomicAdd(&ssq[lane * 4 + 2], acc.z * acc.z);
        atomicAdd(&ssq[lane * 4 + 3], acc.w * acc.w);
    }
    __syncthreads();
    if (tid < 128) {
        atomicAdd(&g_colsum[tid], ssum[tid]);
        atomicAdd(&g_colsumsq[tid], ssq[tid]);
    }
}

// ---------------- K10: BN + ELU + residual (float4) ----------------
__global__ void final_kernel(float* __restrict__ out,
                             const float* __restrict__ gamma, const float* __restrict__ beta) {
    int i = blockIdx.x * blockDim.x + threadIdx.x;   // over N*32 float4s
    if (i >= N_NODES * 32) return;
    int c4 = i & 31;
    const float invN = 1.0f / (float)N_NODES;
    float4 cs = reinterpret_cast<const float4*>(g_colsum)[c4];
    float4 cq = reinterpret_cast<const float4*>(g_colsumsq)[c4];
    float4 gm = reinterpret_cast<const float4*>(gamma)[c4];
    float4 bt = reinterpret_cast<const float4*>(beta)[c4];
    float4 y  = reinterpret_cast<const float4*>(out)[i];
    float4 hv = reinterpret_cast<const float4*>(g_hin)[i];
    float4 r;
    {
        float mu = cs.x * invN, var = cq.x * invN - mu * mu;
        float t = (y.x - mu) * rsqrtf(var + 1e-5f) * gm.x + bt.x;
        r.x = hv.x + (t > 0.f ? t : expm1f(t));
    }
    {
        float mu = cs.y * invN, var = cq.y * invN - mu * mu;
        float t = (y.y - mu) * rsqrtf(var + 1e-5f) * gm.y + bt.y;
        r.y = hv.y + (t > 0.f ? t : expm1f(t));
    }
    {
        float mu = cs.z * invN, var = cq.z * invN - mu * mu;
        float t = (y.z - mu) * rsqrtf(var + 1e-5f) * gm.z + bt.z;
        r.z = hv.z + (t > 0.f ? t : expm1f(t));
    }
    {
        float mu = cs.w * invN, var = cq.w * invN - mu * mu;
        float t = (y.w - mu) * rsqrtf(var + 1e-5f) * gm.w + bt.w;
        r.w = hv.w + (t > 0.f ? t : expm1f(t));
    }
    reinterpret_cast<float4*>(out)[i] = r;
}

// ---------------- launch: forked graph (gemm || edge-CSR pipeline) ----------------
extern "C" void kernel_launch(void* const* d_in, const int* in_sizes, int n_in,
                              void* d_out, int out_size) {
    const float* x        = (const float*)d_in[0];
    const int*   ei       = (const int*)  d_in[1];
    const float* lin_w    = (const float*)d_in[2];
    const float* lin_b    = (const float*)d_in[3];
    const float* gat_w    = (const float*)d_in[4];
    const float* att_src  = (const float*)d_in[5];
    const float* att_dst  = (const float*)d_in[6];
    const float* gat_bias = (const float*)d_in[7];
    const float* bn_gamma = (const float*)d_in[8];
    const float* bn_beta  = (const float*)d_in[9];
    float* out = (float*)d_out;

    cudaFuncSetAttribute(gemm_kernel, cudaFuncAttributeMaxDynamicSharedMemorySize, GEMM_SMEM);

    const int NB = (N_NODES + 1023) / 1024;

    // host-side objects: created during the (single) capture call only; replays
    // execute the captured graph, not this host code.
    cudaStream_t sB;
    cudaStreamCreateWithFlags(&sB, cudaStreamNonBlocking);
    cudaEvent_t evFork, evJoin;
    cudaEventCreateWithFlags(&evFork, cudaEventDisableTiming);
    cudaEventCreateWithFlags(&evJoin, cudaEventDisableTiming);

    // fork: edge pipeline branch (independent of gemm)
    cudaEventRecord(evFork, 0);
    cudaStreamWaitEvent(sB, evFork, 0);

    // main branch: dense GEMM (+ logits)
    gemm_kernel<<<dim3((N_NODES + 63) / 64, 2), 256, GEMM_SMEM, 0>>>(
        x, lin_w, lin_b, gat_w, att_src, att_dst);

    // edge branch: init -> histogram -> scan -> scatter (CSR build)
    init_kernel<<<(N_NODES + 255) / 256, 256, 0, sB>>>();
    count_kernel<<<(M_EDGES + 255) / 256, 256, 0, sB>>>(ei);
    scanA_kernel<<<NB, 256, 0, sB>>>();
    scanB_kernel<<<1, 256, 0, sB>>>(NB);
    scanC_kernel<<<NB, 256, 0, sB>>>();
    scatter_kernel<<<(M_EDGES + 255) / 256, 256, 0, sB>>>(ei);

    // join
    cudaEventRecord(evJoin, sB);
    cudaStreamWaitEvent(0, evJoin, 0);

    agg_kernel<<<(N_NODES + 7) / 8, 256, 0, 0>>>(gat_bias, out);
    final_kernel<<<(N_NODES * 32 + 255) / 256, 256, 0, 0>>>(out, bn_gamma, bn_beta);
}